// round 1
// baseline (speedup 1.0000x reference)
#include <cuda_runtime.h>
#include <math.h>

#define BB 16
#define NN 300000
#define PRE 2000
#define POST 1000
#define NBINS 4096
#define CANDMAX 4096
#define MASKW 32
#define HB 64

__device__ unsigned g_hist[BB][NBINS];
__device__ int g_cut[BB];
__device__ unsigned g_ccount[BB];
__device__ unsigned long long g_cand[BB][CANDMAX];
__device__ float4 g_boxes[BB][PRE];
__device__ int g_nvalid[BB];
__device__ unsigned long long g_mask[BB][PRE][MASKW];

__device__ __forceinline__ unsigned keyf(float f) {
    unsigned u = __float_as_uint(f);
    return u ^ ((u >> 31) ? 0xFFFFFFFFu : 0x80000000u);
}

__global__ void k_zero() {
    int i = blockIdx.x * blockDim.x + threadIdx.x;
    if (i < BB * NBINS) ((unsigned*)g_hist)[i] = 0u;
    if (i < BB) g_ccount[i] = 0u;
}

__global__ void k_hist(const float* __restrict__ cls) {
    __shared__ unsigned sh[NBINS];
    int b = blockIdx.y;
    for (int i = threadIdx.x; i < NBINS; i += blockDim.x) sh[i] = 0u;
    __syncthreads();
    const float* p = cls + (size_t)b * NN;
    for (int i = blockIdx.x * blockDim.x + threadIdx.x; i < NN; i += gridDim.x * blockDim.x)
        atomicAdd(&sh[keyf(p[i]) >> 20], 1u);
    __syncthreads();
    for (int i = threadIdx.x; i < NBINS; i += blockDim.x)
        if (sh[i]) atomicAdd(&g_hist[b][i], sh[i]);
}

__global__ void k_cut() {
    int b = blockIdx.x;
    __shared__ unsigned csum[256];
    unsigned s = 0;
    int base = threadIdx.x * (NBINS / 256);
    for (int i = 0; i < NBINS / 256; i++) s += g_hist[b][base + i];
    csum[threadIdx.x] = s;
    __syncthreads();
    if (threadIdx.x == 0) {
        unsigned acc = 0;
        int cut = 0;
        for (int c = 255; c >= 0; c--) {
            if (acc + csum[c] >= PRE) {
                for (int i = NBINS / 256 - 1; i >= 0; i--) {
                    unsigned h = g_hist[b][c * (NBINS / 256) + i];
                    if (acc + h >= PRE) { cut = c * (NBINS / 256) + i; break; }
                    acc += h;
                }
                g_cut[b] = cut;
                return;
            }
            acc += csum[c];
        }
        g_cut[b] = 0;
    }
}

__global__ void k_compact(const float* __restrict__ cls) {
    int b = blockIdx.y;
    int cut = g_cut[b];
    const float* p = cls + (size_t)b * NN;
    for (int i = blockIdx.x * blockDim.x + threadIdx.x; i < NN; i += gridDim.x * blockDim.x) {
        unsigned k = keyf(p[i]);
        if ((int)(k >> 20) >= cut) {
            unsigned pos = atomicAdd(&g_ccount[b], 1u);
            if (pos < CANDMAX)
                g_cand[b][pos] = ((unsigned long long)k << 32) | (unsigned)(~i);
        }
    }
}

__global__ void __launch_bounds__(1024)
k_sortdecode(const float* __restrict__ reg, const float* __restrict__ anchors) {
    __shared__ unsigned long long sk[CANDMAX];
    __shared__ int swsum[32];
    int b = blockIdx.x;
    int tid = threadIdx.x;
    unsigned n = g_ccount[b];
    if (n > CANDMAX) n = CANDMAX;
    for (int i = tid; i < CANDMAX; i += 1024)
        sk[i] = (i < (int)n) ? g_cand[b][i] : 0ULL;
    __syncthreads();
    // bitonic sort descending
    for (int k = 2; k <= CANDMAX; k <<= 1) {
        for (int j = k >> 1; j > 0; j >>= 1) {
            for (int i = tid; i < CANDMAX; i += 1024) {
                int ixj = i ^ j;
                if (ixj > i) {
                    unsigned long long a = sk[i], c = sk[ixj];
                    bool desc = ((i & k) == 0);
                    if (desc ? (a < c) : (a > c)) { sk[i] = c; sk[ixj] = a; }
                }
            }
            __syncthreads();
        }
    }
    // decode two consecutive elements per thread
    float4 box[2];
    int val[2];
#pragma unroll
    for (int q = 0; q < 2; q++) {
        int e = 2 * tid + q;
        val[q] = 0;
        box[q] = make_float4(0.f, 0.f, 0.f, 0.f);
        if (e < PRE) {
            unsigned idx = ~(unsigned)(sk[e] & 0xFFFFFFFFULL);
            const float* a = anchors + ((size_t)b * NN + idx) * 4;
            const float* r = reg + ((size_t)b * NN + idx) * 4;
            float a0 = a[0], a1 = a[1], a2 = a[2], a3 = a[3];
            float dx = r[0], dy = r[1], dw = r[2], dh = r[3];
            float aw = a2 - a0, ah = a3 - a1;
            float acx = a0 + 0.5f * aw, acy = a1 + 0.5f * ah;
            float pcx = dx * aw + acx, pcy = dy * ah + acy;
            float pw = expf(dw) * aw, ph = expf(dh) * ah;
            float x1 = pcx - 0.5f * pw, y1 = pcy - 0.5f * ph;
            float x2 = pcx + 0.5f * pw, y2 = pcy + 0.5f * ph;
            x1 = fminf(fmaxf(x1, 0.f), 1333.f);
            y1 = fminf(fmaxf(y1, 0.f), 800.f);
            x2 = fminf(fmaxf(x2, 0.f), 1333.f);
            y2 = fminf(fmaxf(y2, 0.f), 800.f);
            float w = x2 - x1, h = y2 - y1;
            val[q] = (w >= 0.001f && h >= 0.001f) ? 1 : 0;
            box[q] = make_float4(x1, y1, x2, y2);
        }
    }
    // block scan of per-thread pair valid counts -> stable partition
    int pairsum = val[0] + val[1];
    int lane = tid & 31, wid = tid >> 5;
    int v = pairsum;
    for (int o = 1; o < 32; o <<= 1) {
        int t = __shfl_up_sync(0xffffffffu, v, o);
        if (lane >= o) v += t;
    }
    if (lane == 31) swsum[wid] = v;
    __syncthreads();
    if (wid == 0) {
        int x = swsum[lane];
        for (int o = 1; o < 32; o <<= 1) {
            int t = __shfl_up_sync(0xffffffffu, x, o);
            if (lane >= o) x += t;
        }
        swsum[lane] = x;
    }
    __syncthreads();
    int incl = v + (wid ? swsum[wid - 1] : 0);
    int excl = incl - pairsum;
    int nv = swsum[31];
    int e0 = 2 * tid, e1 = 2 * tid + 1;
    int rank0 = excl;
    int rank1 = excl + val[0];
    int pos0 = val[0] ? rank0 : nv + (e0 - rank0);
    int pos1 = val[1] ? rank1 : nv + (e1 - rank1);
    if (e0 < PRE) g_boxes[b][pos0] = box[0];
    if (e1 < PRE) g_boxes[b][pos1] = box[1];
    if (tid == 0) g_nvalid[b] = nv;
}

__global__ void k_mask() {
    int b = blockIdx.z;
    int rb = blockIdx.y * 64, cb = blockIdx.x * 64;
    __shared__ float4 cbox[64];
    int t = threadIdx.x;
    int j0 = cb + t;
    cbox[t] = (j0 < PRE) ? g_boxes[b][j0] : make_float4(0.f, 0.f, 0.f, 0.f);
    __syncthreads();
    int i = rb + t;
    if (i >= PRE) return;
    float4 bi = g_boxes[b][i];
    float areai = (bi.z - bi.x) * (bi.w - bi.y);
    unsigned long long bits = 0;
    int lim = min(64, PRE - cb);
    for (int c = 0; c < lim; c++) {
        int j = cb + c;
        float4 bj = cbox[c];
        float ltx = fmaxf(bi.x, bj.x), lty = fmaxf(bi.y, bj.y);
        float rbx = fminf(bi.z, bj.z), rby = fminf(bi.w, bj.w);
        float w = fmaxf(rbx - ltx, 0.f), h = fmaxf(rby - lty, 0.f);
        float inter = w * h;
        float areaj = (bj.z - bj.x) * (bj.w - bj.y);
        float uni = (areai + areaj) - inter;
        float iou = __fdiv_rn(inter, fmaxf(uni, 1e-8f));
        if (j > i && iou > 0.7f) bits |= (1ULL << c);
    }
    g_mask[b][i][blockIdx.x] = bits;
}

__global__ void k_scan(float4* __restrict__ out) {
    int b = blockIdx.x;
    __shared__ int sel[POST];
    __shared__ int skc;
    int tid = threadIdx.x;
    if (tid < 32) {
        int lane = tid;
        int nv = g_nvalid[b];
        int lo = lane * 64;
        unsigned long long rem;
        if (nv <= lo) rem = ~0ULL;
        else if (nv >= lo + 64) rem = 0ULL;
        else rem = (~0ULL) << (nv - lo);
        unsigned long long buf[8];
#pragma unroll
        for (int d = 0; d < 8; d++) buf[d] = g_mask[b][d][lane];
        int kc = 0;
        unsigned long long r = __shfl_sync(0xffffffffu, rem, 0);
        for (int i = 0; i < PRE; i++) {
            unsigned long long m = buf[i & 7];
            int nf = i + 8;
            buf[i & 7] = (nf < PRE) ? g_mask[b][nf][lane] : 0ULL;
            if (!((r >> (i & 63)) & 1ULL)) {
                if (lane == 0 && kc < POST) sel[kc] = i;
                kc++;
                rem |= m;
                r |= __shfl_sync(0xffffffffu, m, i >> 6);
                if (kc >= POST) break;
            }
            if ((i & 63) == 63) {
                r = __shfl_sync(0xffffffffu, rem, (i + 1) >> 6);
            }
        }
        if (lane == 0) skc = (kc < POST) ? kc : POST;
    }
    __syncthreads();
    int kc = skc;
    for (int k = tid; k < POST; k += blockDim.x) {
        float4 v = make_float4(0.f, 0.f, 0.f, 0.f);
        if (k < kc) v = g_boxes[b][sel[k]];
        out[(size_t)b * POST + k] = v;
    }
}

extern "C" void kernel_launch(void* const* d_in, const int* in_sizes, int n_in,
                              void* d_out, int out_size) {
    const float* cls = (const float*)d_in[0];
    const float* reg = (const float*)d_in[1];
    const float* anchors = (const float*)d_in[2];
    float4* out = (float4*)d_out;

    k_zero<<<(BB * NBINS + 255) / 256, 256>>>();
    k_hist<<<dim3(HB, BB), 256>>>(cls);
    k_cut<<<BB, 256>>>();
    k_compact<<<dim3(HB, BB), 256>>>(cls);
    k_sortdecode<<<BB, 1024>>>(reg, anchors);
    k_mask<<<dim3((PRE + 63) / 64, (PRE + 63) / 64, BB), 64>>>();
    k_scan<<<BB, 256>>>(out);
}

// round 2
// speedup vs baseline: 1.2408x; 1.2408x over previous
#include <cuda_runtime.h>
#include <math.h>

#define BB 16
#define NN 300000
#define PRE 2000
#define POST 1000
#define NBINS 4096
#define CANDMAX 4096
#define MASKW 32
#define HB 64

__device__ unsigned g_hist[BB][NBINS];
__device__ int g_cut[BB];
__device__ unsigned g_ccount[BB];
__device__ unsigned long long g_cand[BB][CANDMAX];
__device__ float4 g_boxes[BB][PRE];
__device__ float g_area[BB][PRE];
__device__ int g_nvalid[BB];
__device__ unsigned long long g_mask[BB][PRE][MASKW];

__device__ __forceinline__ unsigned keyf(float f) {
    unsigned u = __float_as_uint(f);
    return u ^ ((u >> 31) ? 0xFFFFFFFFu : 0x80000000u);
}

__global__ void k_zero() {
    int i = blockIdx.x * blockDim.x + threadIdx.x;
    if (i < BB * NBINS) ((unsigned*)g_hist)[i] = 0u;
    if (i < BB) g_ccount[i] = 0u;
}

__global__ void k_hist(const float* __restrict__ cls) {
    __shared__ unsigned sh[NBINS];
    int b = blockIdx.y;
    for (int i = threadIdx.x; i < NBINS; i += blockDim.x) sh[i] = 0u;
    __syncthreads();
    const float4* __restrict__ p = (const float4*)(cls + (size_t)b * NN);
    int stride = gridDim.x * blockDim.x;
    for (int i = blockIdx.x * blockDim.x + threadIdx.x; i < NN / 4; i += stride) {
        float4 v = p[i];
        atomicAdd(&sh[keyf(v.x) >> 20], 1u);
        atomicAdd(&sh[keyf(v.y) >> 20], 1u);
        atomicAdd(&sh[keyf(v.z) >> 20], 1u);
        atomicAdd(&sh[keyf(v.w) >> 20], 1u);
    }
    __syncthreads();
    for (int i = threadIdx.x; i < NBINS; i += blockDim.x)
        if (sh[i]) atomicAdd(&g_hist[b][i], sh[i]);
}

__global__ void k_cut() {
    int b = blockIdx.x;
    __shared__ unsigned csum[256];
    unsigned s = 0;
    int base = threadIdx.x * (NBINS / 256);
    for (int i = 0; i < NBINS / 256; i++) s += g_hist[b][base + i];
    csum[threadIdx.x] = s;
    __syncthreads();
    if (threadIdx.x == 0) {
        unsigned acc = 0;
        int cut = 0;
        for (int c = 255; c >= 0; c--) {
            if (acc + csum[c] >= PRE) {
                for (int i = NBINS / 256 - 1; i >= 0; i--) {
                    unsigned h = g_hist[b][c * (NBINS / 256) + i];
                    if (acc + h >= PRE) { cut = c * (NBINS / 256) + i; break; }
                    acc += h;
                }
                g_cut[b] = cut;
                return;
            }
            acc += csum[c];
        }
        g_cut[b] = 0;
    }
}

__global__ void k_compact(const float* __restrict__ cls) {
    int b = blockIdx.y;
    int cut = g_cut[b];
    const float4* __restrict__ p = (const float4*)(cls + (size_t)b * NN);
    int stride = gridDim.x * blockDim.x;
    for (int i = blockIdx.x * blockDim.x + threadIdx.x; i < NN / 4; i += stride) {
        float4 v = p[i];
        float vv[4] = {v.x, v.y, v.z, v.w};
#pragma unroll
        for (int q = 0; q < 4; q++) {
            unsigned k = keyf(vv[q]);
            if ((int)(k >> 20) >= cut) {
                unsigned pos = atomicAdd(&g_ccount[b], 1u);
                if (pos < CANDMAX)
                    g_cand[b][pos] = ((unsigned long long)k << 32) | (unsigned)(~(4 * i + q));
            }
        }
    }
}

__global__ void __launch_bounds__(1024)
k_sortdecode(const float* __restrict__ reg, const float* __restrict__ anchors) {
    __shared__ unsigned long long sk[CANDMAX];
    __shared__ int swsum[32];
    int b = blockIdx.x;
    int tid = threadIdx.x;
    unsigned n = g_ccount[b];
    if (n > CANDMAX) n = CANDMAX;
    for (int i = tid; i < CANDMAX; i += 1024)
        sk[i] = (i < (int)n) ? g_cand[b][i] : 0ULL;
    __syncthreads();
    // bitonic sort descending
    for (int k = 2; k <= CANDMAX; k <<= 1) {
        for (int j = k >> 1; j > 0; j >>= 1) {
            for (int i = tid; i < CANDMAX; i += 1024) {
                int ixj = i ^ j;
                if (ixj > i) {
                    unsigned long long a = sk[i], c = sk[ixj];
                    bool desc = ((i & k) == 0);
                    if (desc ? (a < c) : (a > c)) { sk[i] = c; sk[ixj] = a; }
                }
            }
            __syncthreads();
        }
    }
    // decode two consecutive elements per thread
    float4 box[2];
    int val[2];
#pragma unroll
    for (int q = 0; q < 2; q++) {
        int e = 2 * tid + q;
        val[q] = 0;
        box[q] = make_float4(0.f, 0.f, 0.f, 0.f);
        if (e < PRE) {
            unsigned idx = ~(unsigned)(sk[e] & 0xFFFFFFFFULL);
            const float* a = anchors + ((size_t)b * NN + idx) * 4;
            const float* r = reg + ((size_t)b * NN + idx) * 4;
            float a0 = a[0], a1 = a[1], a2 = a[2], a3 = a[3];
            float dx = r[0], dy = r[1], dw = r[2], dh = r[3];
            float aw = a2 - a0, ah = a3 - a1;
            float acx = a0 + 0.5f * aw, acy = a1 + 0.5f * ah;
            float pcx = dx * aw + acx, pcy = dy * ah + acy;
            float pw = expf(dw) * aw, ph = expf(dh) * ah;
            float x1 = pcx - 0.5f * pw, y1 = pcy - 0.5f * ph;
            float x2 = pcx + 0.5f * pw, y2 = pcy + 0.5f * ph;
            x1 = fminf(fmaxf(x1, 0.f), 1333.f);
            y1 = fminf(fmaxf(y1, 0.f), 800.f);
            x2 = fminf(fmaxf(x2, 0.f), 1333.f);
            y2 = fminf(fmaxf(y2, 0.f), 800.f);
            float w = x2 - x1, h = y2 - y1;
            val[q] = (w >= 0.001f && h >= 0.001f) ? 1 : 0;
            box[q] = make_float4(x1, y1, x2, y2);
        }
    }
    // block scan of per-thread pair valid counts -> stable partition
    int pairsum = val[0] + val[1];
    int lane = tid & 31, wid = tid >> 5;
    int v = pairsum;
    for (int o = 1; o < 32; o <<= 1) {
        int t = __shfl_up_sync(0xffffffffu, v, o);
        if (lane >= o) v += t;
    }
    if (lane == 31) swsum[wid] = v;
    __syncthreads();
    if (wid == 0) {
        int x = swsum[lane];
        for (int o = 1; o < 32; o <<= 1) {
            int t = __shfl_up_sync(0xffffffffu, x, o);
            if (lane >= o) x += t;
        }
        swsum[lane] = x;
    }
    __syncthreads();
    int incl = v + (wid ? swsum[wid - 1] : 0);
    int excl = incl - pairsum;
    int nv = swsum[31];
    int e0 = 2 * tid, e1 = 2 * tid + 1;
    int rank0 = excl;
    int rank1 = excl + val[0];
    int pos0 = val[0] ? rank0 : nv + (e0 - rank0);
    int pos1 = val[1] ? rank1 : nv + (e1 - rank1);
    if (e0 < PRE) {
        g_boxes[b][pos0] = box[0];
        g_area[b][pos0] = (box[0].z - box[0].x) * (box[0].w - box[0].y);
    }
    if (e1 < PRE) {
        g_boxes[b][pos1] = box[1];
        g_area[b][pos1] = (box[1].z - box[1].x) * (box[1].w - box[1].y);
    }
    if (tid == 0) g_nvalid[b] = nv;
}

// IoU suppression test, exact w.r.t. __fdiv_rn(inter, um) > 0.7f:
// multiply-compare with ambiguity band, rare exact-division fallback.
__device__ __forceinline__ bool sup_test(float inter, float uni) {
    float um = fmaxf(uni, 1e-8f);
    float hi = 0.70000210f * um;  // 0.7*(1+3e-6)
    float lo = 0.69999790f * um;  // 0.7*(1-3e-6)
    bool sup = inter > hi;
    if (!sup && inter >= lo) {    // ambiguous band: exact path (rare)
        sup = (__fdiv_rn(inter, um) > 0.7f);
    }
    return sup;
}

__global__ void __launch_bounds__(64) k_mask() {
    int b = blockIdx.z;
    int rblk = blockIdx.y, cblk = blockIdx.x;
    int t = threadIdx.x;
    int rb = rblk << 6, cb = cblk << 6;
    int i = rb + t;
    if (cblk < rblk) {  // strictly lower triangle: all j < i -> zero word
        if (i < PRE) g_mask[b][i][cblk] = 0ULL;
        return;
    }
    __shared__ float4 cbox[64];
    __shared__ float carea[64];
    {
        int j0 = cb + t;
        float4 bj = (j0 < PRE) ? g_boxes[b][j0] : make_float4(-1.f, -1.f, -1.f, -1.f);
        float aj = (j0 < PRE) ? g_area[b][j0] : 0.f;
        cbox[t] = bj;
        carea[t] = aj;
    }
    __syncthreads();
    if (i >= PRE) return;
    float4 bi = g_boxes[b][i];
    float areai = g_area[b][i];
    unsigned long long bits = 0ULL;
    if (cblk == rblk) {
        for (int c = t + 1; c < 64; c++) {
            float4 bj = cbox[c];
            float w = fmaxf(fminf(bi.z, bj.z) - fmaxf(bi.x, bj.x), 0.f);
            float h = fmaxf(fminf(bi.w, bj.w) - fmaxf(bi.y, bj.y), 0.f);
            float inter = w * h;
            float uni = (areai + carea[c]) - inter;
            if (sup_test(inter, uni)) bits |= (1ULL << c);
        }
    } else {
#pragma unroll
        for (int c = 0; c < 64; c++) {
            float4 bj = cbox[c];
            float w = fmaxf(fminf(bi.z, bj.z) - fmaxf(bi.x, bj.x), 0.f);
            float h = fmaxf(fminf(bi.w, bj.w) - fmaxf(bi.y, bj.y), 0.f);
            float inter = w * h;
            float uni = (areai + carea[c]) - inter;
            if (sup_test(inter, uni)) bits |= (1ULL << c);
        }
    }
    g_mask[b][i][cblk] = bits;
}

__global__ void k_scan(float4* __restrict__ out) {
    int b = blockIdx.x;
    __shared__ int sel[POST];
    __shared__ int skc;
    int tid = threadIdx.x;
    if (tid < 32) {
        int lane = tid;
        int nv = g_nvalid[b];
        int lo = lane * 64;
        unsigned long long rem;
        if (nv <= lo) rem = ~0ULL;
        else if (nv >= lo + 64) rem = 0ULL;
        else rem = (~0ULL) << (nv - lo);
        unsigned long long buf[8];
#pragma unroll
        for (int d = 0; d < 8; d++) buf[d] = g_mask[b][d][lane];
        int kc = 0;
        unsigned long long r = __shfl_sync(0xffffffffu, rem, 0);
        for (int i = 0; i < PRE; i++) {
            unsigned long long m = buf[i & 7];
            int nf = i + 8;
            buf[i & 7] = (nf < PRE) ? g_mask[b][nf][lane] : 0ULL;
            if (!((r >> (i & 63)) & 1ULL)) {
                if (lane == 0 && kc < POST) sel[kc] = i;
                kc++;
                rem |= m;
                r |= __shfl_sync(0xffffffffu, m, i >> 6);
                if (kc >= POST) break;
            }
            if ((i & 63) == 63) {
                r = __shfl_sync(0xffffffffu, rem, (i + 1) >> 6);
            }
        }
        if (lane == 0) skc = (kc < POST) ? kc : POST;
    }
    __syncthreads();
    int kc = skc;
    for (int k = tid; k < POST; k += blockDim.x) {
        float4 v = make_float4(0.f, 0.f, 0.f, 0.f);
        if (k < kc) v = g_boxes[b][sel[k]];
        out[(size_t)b * POST + k] = v;
    }
}

extern "C" void kernel_launch(void* const* d_in, const int* in_sizes, int n_in,
                              void* d_out, int out_size) {
    const float* cls = (const float*)d_in[0];
    const float* reg = (const float*)d_in[1];
    const float* anchors = (const float*)d_in[2];
    float4* out = (float4*)d_out;

    k_zero<<<(BB * NBINS + 255) / 256, 256>>>();
    k_hist<<<dim3(HB, BB), 256>>>(cls);
    k_cut<<<BB, 256>>>();
    k_compact<<<dim3(HB, BB), 256>>>(cls);
    k_sortdecode<<<BB, 1024>>>(reg, anchors);
    k_mask<<<dim3((PRE + 63) / 64, (PRE + 63) / 64, BB), 64>>>();
    k_scan<<<BB, 256>>>(out);
}

// round 3
// speedup vs baseline: 2.4922x; 2.0086x over previous
#include <cuda_runtime.h>
#include <math.h>

#define BB 16
#define NN 300000
#define PRE 2000
#define POST 1000
#define NBINS 4096
#define CANDMAX 4096
#define MASKW 32
#define HB 64

__device__ unsigned g_hist[BB][NBINS];
__device__ int g_cut[BB];
__device__ unsigned g_ccount[BB];
__device__ unsigned long long g_cand[BB][CANDMAX];
__device__ float4 g_boxes[BB][PRE];
__device__ float g_area[BB][PRE];
__device__ int g_nvalid[BB];
__device__ unsigned long long g_mask[BB][PRE][MASKW];

__device__ __forceinline__ unsigned keyf(float f) {
    unsigned u = __float_as_uint(f);
    return u ^ ((u >> 31) ? 0xFFFFFFFFu : 0x80000000u);
}

__device__ __forceinline__ unsigned smaddr(const void* p) {
    return (unsigned)__cvta_generic_to_shared(p);
}
#define CP8(dst, src) asm volatile("cp.async.ca.shared.global [%0], [%1], 8;" :: "r"(dst), "l"(src))
#define CPCOMMIT() asm volatile("cp.async.commit_group;")
#define CPWAIT2() asm volatile("cp.async.wait_group 2;")
#define CPWAITALL() asm volatile("cp.async.wait_all;")

__global__ void k_zero() {
    int i = blockIdx.x * blockDim.x + threadIdx.x;
    if (i < BB * NBINS) ((unsigned*)g_hist)[i] = 0u;
    if (i < BB) g_ccount[i] = 0u;
}

__global__ void k_hist(const float* __restrict__ cls) {
    __shared__ unsigned sh[NBINS];
    int b = blockIdx.y;
    for (int i = threadIdx.x; i < NBINS; i += blockDim.x) sh[i] = 0u;
    __syncthreads();
    const float4* __restrict__ p = (const float4*)(cls + (size_t)b * NN);
    const int NV = NN / 4;
    int stride = gridDim.x * blockDim.x;
    int i0 = blockIdx.x * blockDim.x + threadIdx.x;
    float4 v[5];
    bool in[5];
#pragma unroll
    for (int k = 0; k < 5; k++) {
        int id = i0 + k * stride;
        in[k] = id < NV;
        if (in[k]) v[k] = p[id];
    }
#pragma unroll
    for (int k = 0; k < 5; k++) {
        if (in[k]) {
            atomicAdd(&sh[keyf(v[k].x) >> 20], 1u);
            atomicAdd(&sh[keyf(v[k].y) >> 20], 1u);
            atomicAdd(&sh[keyf(v[k].z) >> 20], 1u);
            atomicAdd(&sh[keyf(v[k].w) >> 20], 1u);
        }
    }
    __syncthreads();
    for (int i = threadIdx.x; i < NBINS; i += blockDim.x)
        if (sh[i]) atomicAdd(&g_hist[b][i], sh[i]);
}

__global__ void k_cut() {
    int b = blockIdx.x;
    __shared__ unsigned csum[256];
    unsigned s = 0;
    int base = threadIdx.x * (NBINS / 256);
    for (int i = 0; i < NBINS / 256; i++) s += g_hist[b][base + i];
    csum[threadIdx.x] = s;
    __syncthreads();
    if (threadIdx.x == 0) {
        unsigned acc = 0;
        int cut = 0;
        for (int c = 255; c >= 0; c--) {
            if (acc + csum[c] >= PRE) {
                for (int i = NBINS / 256 - 1; i >= 0; i--) {
                    unsigned h = g_hist[b][c * (NBINS / 256) + i];
                    if (acc + h >= PRE) { cut = c * (NBINS / 256) + i; break; }
                    acc += h;
                }
                g_cut[b] = cut;
                return;
            }
            acc += csum[c];
        }
        g_cut[b] = 0;
    }
}

__global__ void k_compact(const float* __restrict__ cls) {
    int b = blockIdx.y;
    int cut = g_cut[b];
    const float4* __restrict__ p = (const float4*)(cls + (size_t)b * NN);
    const int NV = NN / 4;
    int stride = gridDim.x * blockDim.x;
    int i0 = blockIdx.x * blockDim.x + threadIdx.x;
    float4 v[5];
    bool in[5];
#pragma unroll
    for (int k = 0; k < 5; k++) {
        int id = i0 + k * stride;
        in[k] = id < NV;
        if (in[k]) v[k] = p[id];
    }
#pragma unroll
    for (int k = 0; k < 5; k++) {
        if (in[k]) {
            int id = i0 + k * stride;
            float vv[4] = {v[k].x, v[k].y, v[k].z, v[k].w};
#pragma unroll
            for (int q = 0; q < 4; q++) {
                unsigned key = keyf(vv[q]);
                if ((int)(key >> 20) >= cut) {
                    unsigned pos = atomicAdd(&g_ccount[b], 1u);
                    if (pos < CANDMAX)
                        g_cand[b][pos] = ((unsigned long long)key << 32) | (unsigned)(~(4 * id + q));
                }
            }
        }
    }
}

__global__ void __launch_bounds__(1024)
k_sortdecode(const float* __restrict__ reg, const float* __restrict__ anchors) {
    __shared__ unsigned long long sk[CANDMAX];
    __shared__ int swsum[32];
    int b = blockIdx.x;
    int tid = threadIdx.x;
    unsigned n = g_ccount[b];
    if (n > CANDMAX) n = CANDMAX;
    for (int i = tid; i < CANDMAX; i += 1024)
        sk[i] = (i < (int)n) ? g_cand[b][i] : 0ULL;
    __syncthreads();
    for (int k = 2; k <= CANDMAX; k <<= 1) {
        for (int j = k >> 1; j > 0; j >>= 1) {
            for (int i = tid; i < CANDMAX; i += 1024) {
                int ixj = i ^ j;
                if (ixj > i) {
                    unsigned long long a = sk[i], c = sk[ixj];
                    bool desc = ((i & k) == 0);
                    if (desc ? (a < c) : (a > c)) { sk[i] = c; sk[ixj] = a; }
                }
            }
            __syncthreads();
        }
    }
    float4 box[2];
    int val[2];
#pragma unroll
    for (int q = 0; q < 2; q++) {
        int e = 2 * tid + q;
        val[q] = 0;
        box[q] = make_float4(0.f, 0.f, 0.f, 0.f);
        if (e < PRE) {
            unsigned idx = ~(unsigned)(sk[e] & 0xFFFFFFFFULL);
            const float* a = anchors + ((size_t)b * NN + idx) * 4;
            const float* r = reg + ((size_t)b * NN + idx) * 4;
            float a0 = a[0], a1 = a[1], a2 = a[2], a3 = a[3];
            float dx = r[0], dy = r[1], dw = r[2], dh = r[3];
            float aw = a2 - a0, ah = a3 - a1;
            float acx = a0 + 0.5f * aw, acy = a1 + 0.5f * ah;
            float pcx = dx * aw + acx, pcy = dy * ah + acy;
            float pw = expf(dw) * aw, ph = expf(dh) * ah;
            float x1 = pcx - 0.5f * pw, y1 = pcy - 0.5f * ph;
            float x2 = pcx + 0.5f * pw, y2 = pcy + 0.5f * ph;
            x1 = fminf(fmaxf(x1, 0.f), 1333.f);
            y1 = fminf(fmaxf(y1, 0.f), 800.f);
            x2 = fminf(fmaxf(x2, 0.f), 1333.f);
            y2 = fminf(fmaxf(y2, 0.f), 800.f);
            float w = x2 - x1, h = y2 - y1;
            val[q] = (w >= 0.001f && h >= 0.001f) ? 1 : 0;
            box[q] = make_float4(x1, y1, x2, y2);
        }
    }
    int pairsum = val[0] + val[1];
    int lane = tid & 31, wid = tid >> 5;
    int v = pairsum;
    for (int o = 1; o < 32; o <<= 1) {
        int t = __shfl_up_sync(0xffffffffu, v, o);
        if (lane >= o) v += t;
    }
    if (lane == 31) swsum[wid] = v;
    __syncthreads();
    if (wid == 0) {
        int x = swsum[lane];
        for (int o = 1; o < 32; o <<= 1) {
            int t = __shfl_up_sync(0xffffffffu, x, o);
            if (lane >= o) x += t;
        }
        swsum[lane] = x;
    }
    __syncthreads();
    int incl = v + (wid ? swsum[wid - 1] : 0);
    int excl = incl - pairsum;
    int nv = swsum[31];
    int e0 = 2 * tid, e1 = 2 * tid + 1;
    int rank0 = excl;
    int rank1 = excl + val[0];
    int pos0 = val[0] ? rank0 : nv + (e0 - rank0);
    int pos1 = val[1] ? rank1 : nv + (e1 - rank1);
    if (e0 < PRE) {
        g_boxes[b][pos0] = box[0];
        g_area[b][pos0] = (box[0].z - box[0].x) * (box[0].w - box[0].y);
    }
    if (e1 < PRE) {
        g_boxes[b][pos1] = box[1];
        g_area[b][pos1] = (box[1].z - box[1].x) * (box[1].w - box[1].y);
    }
    if (tid == 0) g_nvalid[b] = nv;
}

// Upper-triangle only: 528 blocks per image. Branchless IoU test with
// ambiguity bitmask + rare exact-division fixup pass.
__global__ void __launch_bounds__(64) k_mask() {
    int b = blockIdx.y;
    int t = threadIdx.x;
    // map linear tri index -> (rblk, cblk) with cblk >= rblk
    int lin = blockIdx.x, rblk = 0;
    while (lin >= 32 - rblk) { lin -= 32 - rblk; rblk++; }
    int cblk = rblk + lin;
    int rb = rblk << 6, cb = cblk << 6;
    __shared__ float4 cbox[64];
    __shared__ float carea[64];
    {
        int j0 = cb + t;
        cbox[t] = (j0 < PRE) ? g_boxes[b][j0] : make_float4(-1.f, -1.f, -1.f, -1.f);
        carea[t] = (j0 < PRE) ? g_area[b][j0] : 0.f;
    }
    __syncthreads();
    int i = rb + t;
    if (i >= PRE) return;
    float4 bi = g_boxes[b][i];
    float areai = g_area[b][i];
    unsigned long long bits = 0ULL, amb = 0ULL;
    int c0 = (cblk == rblk) ? (t + 1) : 0;
#pragma unroll 8
    for (int c = c0; c < 64; c++) {
        float4 bj = cbox[c];
        float w = fmaxf(fminf(bi.z, bj.z) - fmaxf(bi.x, bj.x), 0.f);
        float h = fmaxf(fminf(bi.w, bj.w) - fmaxf(bi.y, bj.y), 0.f);
        float inter = w * h;
        float um = fmaxf((areai + carea[c]) - inter, 1e-8f);
        bool s1 = inter > 0.70000210f * um;
        bool a1 = (!s1) && (inter >= 0.69999790f * um);
        bits |= ((unsigned long long)s1) << c;
        amb |= ((unsigned long long)a1) << c;
    }
    while (amb) {  // rare exact path
        int c = __ffsll(amb) - 1;
        amb &= amb - 1;
        float4 bj = cbox[c];
        float w = fmaxf(fminf(bi.z, bj.z) - fmaxf(bi.x, bj.x), 0.f);
        float h = fmaxf(fminf(bi.w, bj.w) - fmaxf(bi.y, bj.y), 0.f);
        float inter = w * h;
        float um = fmaxf((areai + carea[c]) - inter, 1e-8f);
        if (__fdiv_rn(inter, um) > 0.7f) bits |= 1ULL << c;
    }
    g_mask[b][i][cblk] = bits;
}

// Serial NMS scan. Mask rows staged through shared via cp.async (4-batch ring,
// 16 rows/batch). Suppressed runs skipped with ffsll. The same-window word is
// read as a broadcast LDS from the staged row (no shfl in the keep chain).
// Lower-triangle words (unwritten by k_mask) are masked out via (lane >= w).
__global__ void __launch_bounds__(256) k_scan(float4* __restrict__ out) {
    __shared__ unsigned long long ring[4][16][32];
    __shared__ int sel[POST];
    __shared__ int skc;
    int b = blockIdx.x;
    int tid = threadIdx.x;
    if (tid < 32) {
        int lane = tid;
        int nv = g_nvalid[b];
        int lo = lane * 64;
        unsigned long long rem;
        if (nv <= lo) rem = ~0ULL;
        else if (nv >= lo + 64) rem = 0ULL;
        else rem = (~0ULL) << (nv - lo);
        // prologue: stage batches 0..2
        for (int nb = 0; nb < 3; nb++) {
#pragma unroll
            for (int q = 0; q < 16; q++)
                CP8(smaddr(&ring[nb][q][lane]), &g_mask[b][nb * 16 + q][lane]);
            CPCOMMIT();
        }
        int limit = (PRE < nv) ? PRE : nv;
        int i = 0, kc = 0, w = 0;
        unsigned long long r = 0ULL;
        bool done = false;
        for (int bt = 0; bt < PRE / 16 && !done; bt++) {
            CPWAIT2();
            __syncwarp();
            int base = bt * 16;
            if (base < limit) {
                if ((base & 63) == 0) {
                    w = base >> 6;
                    r = __shfl_sync(0xffffffffu, rem, w);
                }
                int bend = base + 16;
                if (bend > limit) bend = limit;
                while (i < bend) {
                    unsigned long long rr = r >> (i & 63);
                    if (rr & 1ULL) {
                        unsigned long long inv = ~rr;
                        i += inv ? (__ffsll(inv) - 1) : (64 - (i & 63));
                        continue;
                    }
                    unsigned long long mrow = ring[bt & 3][i & 15][lane];
                    unsigned long long mdia = ring[bt & 3][i & 15][w];
                    if (lane == 0) sel[kc] = i;
                    kc++;
                    rem |= (lane >= w) ? mrow : 0ULL;
                    r |= mdia;
                    if (kc >= POST) { done = true; break; }
                    i++;
                }
            }
            int nb = bt + 3;
            if (nb < PRE / 16) {
#pragma unroll
                for (int q = 0; q < 16; q++)
                    CP8(smaddr(&ring[nb & 3][q][lane]), &g_mask[b][nb * 16 + q][lane]);
            }
            CPCOMMIT();
        }
        CPWAITALL();
        if (lane == 0) skc = kc;
    }
    __syncthreads();
    int kc = skc;
    for (int k = tid; k < POST; k += blockDim.x) {
        float4 v = make_float4(0.f, 0.f, 0.f, 0.f);
        if (k < kc) v = g_boxes[b][sel[k]];
        out[(size_t)b * POST + k] = v;
    }
}

extern "C" void kernel_launch(void* const* d_in, const int* in_sizes, int n_in,
                              void* d_out, int out_size) {
    const float* cls = (const float*)d_in[0];
    const float* reg = (const float*)d_in[1];
    const float* anchors = (const float*)d_in[2];
    float4* out = (float4*)d_out;

    k_zero<<<(BB * NBINS + 255) / 256, 256>>>();
    k_hist<<<dim3(HB, BB), 256>>>(cls);
    k_cut<<<BB, 256>>>();
    k_compact<<<dim3(HB, BB), 256>>>(cls);
    k_sortdecode<<<BB, 1024>>>(reg, anchors);
    k_mask<<<dim3(528, BB), 64>>>();
    k_scan<<<BB, 256>>>(out);
}

// round 4
// speedup vs baseline: 2.8159x; 1.1299x over previous
#include <cuda_runtime.h>
#include <math.h>

#define BB 16
#define NN 300000
#define NV 75000
#define PRE 2000
#define POST 1000
#define NBINS 4096
#define CANDMAX 4096
#define MASKW 32
#define STAGE 1024

__device__ unsigned g_hist[BB][NBINS];
__device__ int g_cut[BB];
__device__ int g_need[BB];
__device__ unsigned g_ccount[BB];
__device__ unsigned long long g_cand[BB][CANDMAX];
__device__ float4 g_boxes[BB][PRE];
__device__ float g_area[BB][PRE];
__device__ int g_nvalid[BB];
__device__ unsigned long long g_mask[BB][PRE][MASKW];

__device__ __forceinline__ unsigned keyf(float f) {
    unsigned u = __float_as_uint(f);
    return u ^ ((u >> 31) ? 0xFFFFFFFFu : 0x80000000u);
}

__device__ __forceinline__ unsigned smaddr(const void* p) {
    return (unsigned)__cvta_generic_to_shared(p);
}
#define CP8(dst, src) asm volatile("cp.async.ca.shared.global [%0], [%1], 8;" :: "r"(dst), "l"(src))
#define CPCOMMIT() asm volatile("cp.async.commit_group;")
#define CPWAIT2() asm volatile("cp.async.wait_group 2;")
#define CPWAITALL() asm volatile("cp.async.wait_all;")

__global__ void k_zero() {
    int i = blockIdx.x * blockDim.x + threadIdx.x;
    if (i < BB * NBINS) ((unsigned*)g_hist)[i] = 0u;
    if (i < BB) g_ccount[i] = 0u;
}

// Histogram upper half only (non-negative scores). 8 float4/thread tiles,
// only the last block per image predicated.
__global__ void __launch_bounds__(256) k_hist(const float* __restrict__ cls) {
    __shared__ unsigned sh[2048];
    int b = blockIdx.y;
    int t = threadIdx.x;
    for (int i = t; i < 2048; i += 256) sh[i] = 0u;
    __syncthreads();
    const float4* __restrict__ p = (const float4*)(cls + (size_t)b * NN);
    int base = blockIdx.x * 2048;
    if (base + 2048 <= NV) {
        float4 v[8];
#pragma unroll
        for (int k = 0; k < 8; k++) v[k] = p[base + t + 256 * k];
#pragma unroll
        for (int k = 0; k < 8; k++) {
            unsigned kk[4] = {keyf(v[k].x), keyf(v[k].y), keyf(v[k].z), keyf(v[k].w)};
#pragma unroll
            for (int q = 0; q < 4; q++)
                if (kk[q] >= 0x80000000u) atomicAdd(&sh[(kk[q] >> 20) - 2048], 1u);
        }
    } else {
        for (int k = 0; k < 8; k++) {
            int id = base + t + 256 * k;
            if (id < NV) {
                float4 v = p[id];
                unsigned kk[4] = {keyf(v.x), keyf(v.y), keyf(v.z), keyf(v.w)};
#pragma unroll
                for (int q = 0; q < 4; q++)
                    if (kk[q] >= 0x80000000u) atomicAdd(&sh[(kk[q] >> 20) - 2048], 1u);
            }
        }
    }
    __syncthreads();
    for (int i = t; i < 2048; i += 256) {
        unsigned c = sh[i];
        if (c) atomicAdd(&g_hist[b][2048 + i], c);
    }
}

__global__ void k_cutA() {
    int b = blockIdx.x;
    __shared__ unsigned csum[256];
    unsigned s = 0;
    int base = 2048 + threadIdx.x * 8;
    for (int i = 0; i < 8; i++) s += g_hist[b][base + i];
    csum[threadIdx.x] = s;
    __syncthreads();
    if (threadIdx.x == 0) {
        unsigned acc = 0;
        int found = 0;
        for (int c = 255; c >= 0; c--) {
            if (acc + csum[c] >= PRE) {
                for (int i = 7; i >= 0; i--) {
                    unsigned h = g_hist[b][2048 + c * 8 + i];
                    if (acc + h >= PRE) { g_cut[b] = 2048 + c * 8 + i; found = 1; break; }
                    acc += h;
                }
                break;
            }
            acc += csum[c];
        }
        g_need[b] = !found;
        if (!found) g_cut[b] = 0;
    }
}

// Fallback: lower-half histogram, only for flagged images (no-op otherwise).
__global__ void __launch_bounds__(256) k_hist2(const float* __restrict__ cls) {
    int b = blockIdx.y;
    if (g_need[b] == 0) return;
    __shared__ unsigned sh[2048];
    int t = threadIdx.x;
    for (int i = t; i < 2048; i += 256) sh[i] = 0u;
    __syncthreads();
    const float4* __restrict__ p = (const float4*)(cls + (size_t)b * NN);
    int base = blockIdx.x * 2048;
    for (int k = 0; k < 8; k++) {
        int id = base + t + 256 * k;
        if (id < NV) {
            float4 v = p[id];
            unsigned kk[4] = {keyf(v.x), keyf(v.y), keyf(v.z), keyf(v.w)};
#pragma unroll
            for (int q = 0; q < 4; q++)
                if (kk[q] < 0x80000000u) atomicAdd(&sh[kk[q] >> 20], 1u);
        }
    }
    __syncthreads();
    for (int i = t; i < 2048; i += 256) {
        unsigned c = sh[i];
        if (c) atomicAdd(&g_hist[b][i], c);
    }
}

__global__ void k_cutB() {
    int b = blockIdx.x;
    if (g_need[b] == 0) return;
    __shared__ unsigned csum[256];
    unsigned s = 0;
    int base = threadIdx.x * 16;
    for (int i = 0; i < 16; i++) s += g_hist[b][base + i];
    csum[threadIdx.x] = s;
    __syncthreads();
    if (threadIdx.x == 0) {
        unsigned acc = 0;
        for (int c = 255; c >= 0; c--) {
            if (acc + csum[c] >= PRE) {
                for (int i = 15; i >= 0; i--) {
                    unsigned h = g_hist[b][c * 16 + i];
                    if (acc + h >= PRE) { g_cut[b] = c * 16 + i; return; }
                    acc += h;
                }
                return;
            }
            acc += csum[c];
        }
        g_cut[b] = 0;
    }
}

// Compact with block-aggregated global atomic: stage in shared, ONE
// atomicAdd(g_ccount) per block instead of ~2500 contended per image.
__global__ void __launch_bounds__(256) k_compact(const float* __restrict__ cls) {
    __shared__ unsigned long long stage[STAGE];
    __shared__ unsigned s_cnt, s_base;
    int b = blockIdx.y;
    int t = threadIdx.x;
    int cut = g_cut[b];
    if (t == 0) s_cnt = 0u;
    __syncthreads();
    const float4* __restrict__ p = (const float4*)(cls + (size_t)b * NN);
    int base = blockIdx.x * 2048;
    if (base + 2048 <= NV) {
        float4 v[8];
#pragma unroll
        for (int k = 0; k < 8; k++) v[k] = p[base + t + 256 * k];
#pragma unroll
        for (int k = 0; k < 8; k++) {
            int id = base + t + 256 * k;
            unsigned kk[4] = {keyf(v[k].x), keyf(v[k].y), keyf(v[k].z), keyf(v[k].w)};
#pragma unroll
            for (int q = 0; q < 4; q++) {
                if ((int)(kk[q] >> 20) >= cut) {
                    unsigned r = atomicAdd(&s_cnt, 1u);
                    if (r < STAGE)
                        stage[r] = ((unsigned long long)kk[q] << 32) | (unsigned)(~(4 * id + q));
                }
            }
        }
    } else {
        for (int k = 0; k < 8; k++) {
            int id = base + t + 256 * k;
            if (id < NV) {
                float4 v = p[id];
                unsigned kk[4] = {keyf(v.x), keyf(v.y), keyf(v.z), keyf(v.w)};
#pragma unroll
                for (int q = 0; q < 4; q++) {
                    if ((int)(kk[q] >> 20) >= cut) {
                        unsigned r = atomicAdd(&s_cnt, 1u);
                        if (r < STAGE)
                            stage[r] = ((unsigned long long)kk[q] << 32) | (unsigned)(~(4 * id + q));
                    }
                }
            }
        }
    }
    __syncthreads();
    if (t == 0) {
        unsigned c = s_cnt < STAGE ? s_cnt : STAGE;
        s_base = atomicAdd(&g_ccount[b], c);
    }
    __syncthreads();
    unsigned c = s_cnt < STAGE ? s_cnt : STAGE;
    for (unsigned r = t; r < c; r += 256) {
        unsigned pos = s_base + r;
        if (pos < CANDMAX) g_cand[b][pos] = stage[r];
    }
}

__global__ void __launch_bounds__(1024)
k_sortdecode(const float* __restrict__ reg, const float* __restrict__ anchors) {
    __shared__ unsigned long long sk[CANDMAX];
    __shared__ int swsum[32];
    int b = blockIdx.x;
    int tid = threadIdx.x;
    unsigned n = g_ccount[b];
    if (n > CANDMAX) n = CANDMAX;
    for (int i = tid; i < CANDMAX; i += 1024)
        sk[i] = (i < (int)n) ? g_cand[b][i] : 0ULL;
    __syncthreads();
    for (int k = 2; k <= CANDMAX; k <<= 1) {
        for (int j = k >> 1; j > 0; j >>= 1) {
            for (int i = tid; i < CANDMAX; i += 1024) {
                int ixj = i ^ j;
                if (ixj > i) {
                    unsigned long long a = sk[i], c = sk[ixj];
                    bool desc = ((i & k) == 0);
                    if (desc ? (a < c) : (a > c)) { sk[i] = c; sk[ixj] = a; }
                }
            }
            __syncthreads();
        }
    }
    float4 box[2];
    int val[2];
#pragma unroll
    for (int q = 0; q < 2; q++) {
        int e = 2 * tid + q;
        val[q] = 0;
        box[q] = make_float4(0.f, 0.f, 0.f, 0.f);
        if (e < PRE) {
            unsigned idx = ~(unsigned)(sk[e] & 0xFFFFFFFFULL);
            const float* a = anchors + ((size_t)b * NN + idx) * 4;
            const float* r = reg + ((size_t)b * NN + idx) * 4;
            float a0 = a[0], a1 = a[1], a2 = a[2], a3 = a[3];
            float dx = r[0], dy = r[1], dw = r[2], dh = r[3];
            float aw = a2 - a0, ah = a3 - a1;
            float acx = a0 + 0.5f * aw, acy = a1 + 0.5f * ah;
            float pcx = dx * aw + acx, pcy = dy * ah + acy;
            float pw = expf(dw) * aw, ph = expf(dh) * ah;
            float x1 = pcx - 0.5f * pw, y1 = pcy - 0.5f * ph;
            float x2 = pcx + 0.5f * pw, y2 = pcy + 0.5f * ph;
            x1 = fminf(fmaxf(x1, 0.f), 1333.f);
            y1 = fminf(fmaxf(y1, 0.f), 800.f);
            x2 = fminf(fmaxf(x2, 0.f), 1333.f);
            y2 = fminf(fmaxf(y2, 0.f), 800.f);
            float w = x2 - x1, h = y2 - y1;
            val[q] = (w >= 0.001f && h >= 0.001f) ? 1 : 0;
            box[q] = make_float4(x1, y1, x2, y2);
        }
    }
    int pairsum = val[0] + val[1];
    int lane = tid & 31, wid = tid >> 5;
    int v = pairsum;
    for (int o = 1; o < 32; o <<= 1) {
        int t = __shfl_up_sync(0xffffffffu, v, o);
        if (lane >= o) v += t;
    }
    if (lane == 31) swsum[wid] = v;
    __syncthreads();
    if (wid == 0) {
        int x = swsum[lane];
        for (int o = 1; o < 32; o <<= 1) {
            int t = __shfl_up_sync(0xffffffffu, x, o);
            if (lane >= o) x += t;
        }
        swsum[lane] = x;
    }
    __syncthreads();
    int incl = v + (wid ? swsum[wid - 1] : 0);
    int excl = incl - pairsum;
    int nv = swsum[31];
    int e0 = 2 * tid, e1 = 2 * tid + 1;
    int rank0 = excl;
    int rank1 = excl + val[0];
    int pos0 = val[0] ? rank0 : nv + (e0 - rank0);
    int pos1 = val[1] ? rank1 : nv + (e1 - rank1);
    if (e0 < PRE) {
        g_boxes[b][pos0] = box[0];
        g_area[b][pos0] = (box[0].z - box[0].x) * (box[0].w - box[0].y);
    }
    if (e1 < PRE) {
        g_boxes[b][pos1] = box[1];
        g_area[b][pos1] = (box[1].z - box[1].x) * (box[1].w - box[1].y);
    }
    if (tid == 0) g_nvalid[b] = nv;
}

__global__ void __launch_bounds__(64) k_mask() {
    int b = blockIdx.y;
    int t = threadIdx.x;
    int lin = blockIdx.x, rblk = 0;
    while (lin >= 32 - rblk) { lin -= 32 - rblk; rblk++; }
    int cblk = rblk + lin;
    int rb = rblk << 6, cb = cblk << 6;
    __shared__ float4 cbox[64];
    __shared__ float carea[64];
    {
        int j0 = cb + t;
        cbox[t] = (j0 < PRE) ? g_boxes[b][j0] : make_float4(-1.f, -1.f, -1.f, -1.f);
        carea[t] = (j0 < PRE) ? g_area[b][j0] : 0.f;
    }
    __syncthreads();
    int i = rb + t;
    if (i >= PRE) return;
    float4 bi = g_boxes[b][i];
    float areai = g_area[b][i];
    unsigned long long bits = 0ULL, amb = 0ULL;
    int c0 = (cblk == rblk) ? (t + 1) : 0;
#pragma unroll 8
    for (int c = c0; c < 64; c++) {
        float4 bj = cbox[c];
        float w = fmaxf(fminf(bi.z, bj.z) - fmaxf(bi.x, bj.x), 0.f);
        float h = fmaxf(fminf(bi.w, bj.w) - fmaxf(bi.y, bj.y), 0.f);
        float inter = w * h;
        float um = fmaxf((areai + carea[c]) - inter, 1e-8f);
        bool s1 = inter > 0.70000210f * um;
        bool a1 = (!s1) && (inter >= 0.69999790f * um);
        bits |= ((unsigned long long)s1) << c;
        amb |= ((unsigned long long)a1) << c;
    }
    while (amb) {
        int c = __ffsll(amb) - 1;
        amb &= amb - 1;
        float4 bj = cbox[c];
        float w = fmaxf(fminf(bi.z, bj.z) - fmaxf(bi.x, bj.x), 0.f);
        float h = fmaxf(fminf(bi.w, bj.w) - fmaxf(bi.y, bj.y), 0.f);
        float inter = w * h;
        float um = fmaxf((areai + carea[c]) - inter, 1e-8f);
        if (__fdiv_rn(inter, um) > 0.7f) bits |= 1ULL << c;
    }
    g_mask[b][i][cblk] = bits;
}

__global__ void __launch_bounds__(256) k_scan(float4* __restrict__ out) {
    __shared__ unsigned long long ring[4][16][32];
    __shared__ int sel[POST];
    __shared__ int skc;
    int b = blockIdx.x;
    int tid = threadIdx.x;
    if (tid < 32) {
        int lane = tid;
        int nv = g_nvalid[b];
        int lo = lane * 64;
        unsigned long long rem;
        if (nv <= lo) rem = ~0ULL;
        else if (nv >= lo + 64) rem = 0ULL;
        else rem = (~0ULL) << (nv - lo);
        for (int nb = 0; nb < 3; nb++) {
#pragma unroll
            for (int q = 0; q < 16; q++)
                CP8(smaddr(&ring[nb][q][lane]), &g_mask[b][nb * 16 + q][lane]);
            CPCOMMIT();
        }
        int limit = (PRE < nv) ? PRE : nv;
        int i = 0, kc = 0, w = 0;
        unsigned long long r = 0ULL;
        bool done = false;
        for (int bt = 0; bt < PRE / 16 && !done; bt++) {
            CPWAIT2();
            __syncwarp();
            int base = bt * 16;
            if (base < limit) {
                if ((base & 63) == 0) {
                    w = base >> 6;
                    r = __shfl_sync(0xffffffffu, rem, w);
                }
                int bend = base + 16;
                if (bend > limit) bend = limit;
                while (i < bend) {
                    unsigned long long rr = r >> (i & 63);
                    if (rr & 1ULL) {
                        unsigned long long inv = ~rr;
                        i += inv ? (__ffsll(inv) - 1) : (64 - (i & 63));
                        continue;
                    }
                    unsigned long long mrow = ring[bt & 3][i & 15][lane];
                    unsigned long long mdia = ring[bt & 3][i & 15][w];
                    if (lane == 0) sel[kc] = i;
                    kc++;
                    rem |= (lane >= w) ? mrow : 0ULL;
                    r |= mdia;
                    if (kc >= POST) { done = true; break; }
                    i++;
                }
            }
            int nb = bt + 3;
            if (nb < PRE / 16) {
#pragma unroll
                for (int q = 0; q < 16; q++)
                    CP8(smaddr(&ring[nb & 3][q][lane]), &g_mask[b][nb * 16 + q][lane]);
            }
            CPCOMMIT();
        }
        CPWAITALL();
        if (lane == 0) skc = kc;
    }
    __syncthreads();
    int kc = skc;
    for (int k = tid; k < POST; k += blockDim.x) {
        float4 v = make_float4(0.f, 0.f, 0.f, 0.f);
        if (k < kc) v = g_boxes[b][sel[k]];
        out[(size_t)b * POST + k] = v;
    }
}

extern "C" void kernel_launch(void* const* d_in, const int* in_sizes, int n_in,
                              void* d_out, int out_size) {
    const float* cls = (const float*)d_in[0];
    const float* reg = (const float*)d_in[1];
    const float* anchors = (const float*)d_in[2];
    float4* out = (float4*)d_out;

    k_zero<<<(BB * NBINS + 255) / 256, 256>>>();
    k_hist<<<dim3(37, BB), 256>>>(cls);
    k_cutA<<<BB, 256>>>();
    k_hist2<<<dim3(37, BB), 256>>>(cls);
    k_cutB<<<BB, 256>>>();
    k_compact<<<dim3(37, BB), 256>>>(cls);
    k_sortdecode<<<BB, 1024>>>(reg, anchors);
    k_mask<<<dim3(528, BB), 64>>>();
    k_scan<<<BB, 256>>>(out);
}

// round 5
// speedup vs baseline: 3.2953x; 1.1703x over previous
#include <cuda_runtime.h>
#include <math.h>

#define BB 16
#define NN 300000
#define NV 75000
#define PRE 2000
#define POST 1000
#define NBINS 4096
#define CANDMAX 4096
#define MASKW 32
#define STAGE 1024

__device__ unsigned g_hist[BB][NBINS];
__device__ int g_cut[BB];
__device__ int g_need[BB];
__device__ unsigned g_ccount[BB];
__device__ unsigned long long g_cand[BB][CANDMAX];
__device__ float4 g_boxes[BB][PRE];
__device__ float g_area[BB][PRE];
__device__ int g_nvalid[BB];
__device__ unsigned long long g_mask[BB][PRE][MASKW];

__device__ __forceinline__ unsigned keyf(float f) {
    unsigned u = __float_as_uint(f);
    return u ^ ((u >> 31) ? 0xFFFFFFFFu : 0x80000000u);
}

__device__ __forceinline__ unsigned smaddr(const void* p) {
    return (unsigned)__cvta_generic_to_shared(p);
}
#define CP8(dst, src) asm volatile("cp.async.ca.shared.global [%0], [%1], 8;" :: "r"(dst), "l"(src))
#define CPCOMMIT() asm volatile("cp.async.commit_group;")
#define CPWAIT2() asm volatile("cp.async.wait_group 2;")
#define CPWAITALL() asm volatile("cp.async.wait_all;")

__global__ void k_zero() {
    int i = blockIdx.x * blockDim.x + threadIdx.x;
    if (i < BB * NBINS) ((unsigned*)g_hist)[i] = 0u;
    if (i < BB) g_ccount[i] = 0u;
}

__global__ void __launch_bounds__(256) k_hist(const float* __restrict__ cls) {
    __shared__ unsigned sh[2048];
    int b = blockIdx.y;
    int t = threadIdx.x;
    for (int i = t; i < 2048; i += 256) sh[i] = 0u;
    __syncthreads();
    const float4* __restrict__ p = (const float4*)(cls + (size_t)b * NN);
    int base = blockIdx.x * 2048;
    if (base + 2048 <= NV) {
        float4 v[8];
#pragma unroll
        for (int k = 0; k < 8; k++) v[k] = p[base + t + 256 * k];
#pragma unroll
        for (int k = 0; k < 8; k++) {
            unsigned kk[4] = {keyf(v[k].x), keyf(v[k].y), keyf(v[k].z), keyf(v[k].w)};
#pragma unroll
            for (int q = 0; q < 4; q++)
                if (kk[q] >= 0x80000000u) atomicAdd(&sh[(kk[q] >> 20) - 2048], 1u);
        }
    } else {
        for (int k = 0; k < 8; k++) {
            int id = base + t + 256 * k;
            if (id < NV) {
                float4 v = p[id];
                unsigned kk[4] = {keyf(v.x), keyf(v.y), keyf(v.z), keyf(v.w)};
#pragma unroll
                for (int q = 0; q < 4; q++)
                    if (kk[q] >= 0x80000000u) atomicAdd(&sh[(kk[q] >> 20) - 2048], 1u);
            }
        }
    }
    __syncthreads();
    for (int i = t; i < 2048; i += 256) {
        unsigned c = sh[i];
        if (c) atomicAdd(&g_hist[b][2048 + i], c);
    }
}

__global__ void k_cutA() {
    int b = blockIdx.x;
    __shared__ unsigned csum[256];
    unsigned s = 0;
    int base = 2048 + threadIdx.x * 8;
    for (int i = 0; i < 8; i++) s += g_hist[b][base + i];
    csum[threadIdx.x] = s;
    __syncthreads();
    if (threadIdx.x == 0) {
        unsigned acc = 0;
        int found = 0;
        for (int c = 255; c >= 0; c--) {
            if (acc + csum[c] >= PRE) {
                for (int i = 7; i >= 0; i--) {
                    unsigned h = g_hist[b][2048 + c * 8 + i];
                    if (acc + h >= PRE) { g_cut[b] = 2048 + c * 8 + i; found = 1; break; }
                    acc += h;
                }
                break;
            }
            acc += csum[c];
        }
        g_need[b] = !found;
        if (!found) g_cut[b] = 0;
    }
}

__global__ void __launch_bounds__(256) k_hist2(const float* __restrict__ cls) {
    int b = blockIdx.y;
    if (g_need[b] == 0) return;
    __shared__ unsigned sh[2048];
    int t = threadIdx.x;
    for (int i = t; i < 2048; i += 256) sh[i] = 0u;
    __syncthreads();
    const float4* __restrict__ p = (const float4*)(cls + (size_t)b * NN);
    int base = blockIdx.x * 2048;
    for (int k = 0; k < 8; k++) {
        int id = base + t + 256 * k;
        if (id < NV) {
            float4 v = p[id];
            unsigned kk[4] = {keyf(v.x), keyf(v.y), keyf(v.z), keyf(v.w)};
#pragma unroll
            for (int q = 0; q < 4; q++)
                if (kk[q] < 0x80000000u) atomicAdd(&sh[kk[q] >> 20], 1u);
        }
    }
    __syncthreads();
    for (int i = t; i < 2048; i += 256) {
        unsigned c = sh[i];
        if (c) atomicAdd(&g_hist[b][i], c);
    }
}

__global__ void k_cutB() {
    int b = blockIdx.x;
    if (g_need[b] == 0) return;
    __shared__ unsigned csum[256];
    unsigned s = 0;
    int base = threadIdx.x * 16;
    for (int i = 0; i < 16; i++) s += g_hist[b][base + i];
    csum[threadIdx.x] = s;
    __syncthreads();
    if (threadIdx.x == 0) {
        unsigned acc = 0;
        for (int c = 255; c >= 0; c--) {
            if (acc + csum[c] >= PRE) {
                for (int i = 15; i >= 0; i--) {
                    unsigned h = g_hist[b][c * 16 + i];
                    if (acc + h >= PRE) { g_cut[b] = c * 16 + i; return; }
                    acc += h;
                }
                return;
            }
            acc += csum[c];
        }
        g_cut[b] = 0;
    }
}

__global__ void __launch_bounds__(256) k_compact(const float* __restrict__ cls) {
    __shared__ unsigned long long stage[STAGE];
    __shared__ unsigned s_cnt, s_base;
    int b = blockIdx.y;
    int t = threadIdx.x;
    int cut = g_cut[b];
    if (t == 0) s_cnt = 0u;
    __syncthreads();
    const float4* __restrict__ p = (const float4*)(cls + (size_t)b * NN);
    int base = blockIdx.x * 2048;
    if (base + 2048 <= NV) {
        float4 v[8];
#pragma unroll
        for (int k = 0; k < 8; k++) v[k] = p[base + t + 256 * k];
#pragma unroll
        for (int k = 0; k < 8; k++) {
            int id = base + t + 256 * k;
            unsigned kk[4] = {keyf(v[k].x), keyf(v[k].y), keyf(v[k].z), keyf(v[k].w)};
#pragma unroll
            for (int q = 0; q < 4; q++) {
                if ((int)(kk[q] >> 20) >= cut) {
                    unsigned r = atomicAdd(&s_cnt, 1u);
                    if (r < STAGE)
                        stage[r] = ((unsigned long long)kk[q] << 32) | (unsigned)(~(4 * id + q));
                }
            }
        }
    } else {
        for (int k = 0; k < 8; k++) {
            int id = base + t + 256 * k;
            if (id < NV) {
                float4 v = p[id];
                unsigned kk[4] = {keyf(v.x), keyf(v.y), keyf(v.z), keyf(v.w)};
#pragma unroll
                for (int q = 0; q < 4; q++) {
                    if ((int)(kk[q] >> 20) >= cut) {
                        unsigned r = atomicAdd(&s_cnt, 1u);
                        if (r < STAGE)
                            stage[r] = ((unsigned long long)kk[q] << 32) | (unsigned)(~(4 * id + q));
                    }
                }
            }
        }
    }
    __syncthreads();
    if (t == 0) {
        unsigned c = s_cnt < STAGE ? s_cnt : STAGE;
        s_base = atomicAdd(&g_ccount[b], c);
    }
    __syncthreads();
    unsigned c = s_cnt < STAGE ? s_cnt : STAGE;
    for (unsigned r = t; r < c; r += 256) {
        unsigned pos = s_base + r;
        if (pos < CANDMAX) g_cand[b][pos] = stage[r];
    }
}

__global__ void __launch_bounds__(1024)
k_sortdecode(const float* __restrict__ reg, const float* __restrict__ anchors) {
    __shared__ unsigned long long sk[CANDMAX];
    __shared__ int swsum[32];
    int b = blockIdx.x;
    int tid = threadIdx.x;
    unsigned n = g_ccount[b];
    if (n > CANDMAX) n = CANDMAX;
    for (int i = tid; i < CANDMAX; i += 1024)
        sk[i] = (i < (int)n) ? g_cand[b][i] : 0ULL;
    __syncthreads();
    for (int k = 2; k <= CANDMAX; k <<= 1) {
        for (int j = k >> 1; j > 0; j >>= 1) {
            for (int i = tid; i < CANDMAX; i += 1024) {
                int ixj = i ^ j;
                if (ixj > i) {
                    unsigned long long a = sk[i], c = sk[ixj];
                    bool desc = ((i & k) == 0);
                    if (desc ? (a < c) : (a > c)) { sk[i] = c; sk[ixj] = a; }
                }
            }
            __syncthreads();
        }
    }
    float4 box[2];
    int val[2];
#pragma unroll
    for (int q = 0; q < 2; q++) {
        int e = 2 * tid + q;
        val[q] = 0;
        box[q] = make_float4(0.f, 0.f, 0.f, 0.f);
        if (e < PRE) {
            unsigned idx = ~(unsigned)(sk[e] & 0xFFFFFFFFULL);
            const float* a = anchors + ((size_t)b * NN + idx) * 4;
            const float* r = reg + ((size_t)b * NN + idx) * 4;
            float a0 = a[0], a1 = a[1], a2 = a[2], a3 = a[3];
            float dx = r[0], dy = r[1], dw = r[2], dh = r[3];
            float aw = a2 - a0, ah = a3 - a1;
            float acx = a0 + 0.5f * aw, acy = a1 + 0.5f * ah;
            float pcx = dx * aw + acx, pcy = dy * ah + acy;
            float pw = expf(dw) * aw, ph = expf(dh) * ah;
            float x1 = pcx - 0.5f * pw, y1 = pcy - 0.5f * ph;
            float x2 = pcx + 0.5f * pw, y2 = pcy + 0.5f * ph;
            x1 = fminf(fmaxf(x1, 0.f), 1333.f);
            y1 = fminf(fmaxf(y1, 0.f), 800.f);
            x2 = fminf(fmaxf(x2, 0.f), 1333.f);
            y2 = fminf(fmaxf(y2, 0.f), 800.f);
            float w = x2 - x1, h = y2 - y1;
            val[q] = (w >= 0.001f && h >= 0.001f) ? 1 : 0;
            box[q] = make_float4(x1, y1, x2, y2);
        }
    }
    int pairsum = val[0] + val[1];
    int lane = tid & 31, wid = tid >> 5;
    int v = pairsum;
    for (int o = 1; o < 32; o <<= 1) {
        int t = __shfl_up_sync(0xffffffffu, v, o);
        if (lane >= o) v += t;
    }
    if (lane == 31) swsum[wid] = v;
    __syncthreads();
    if (wid == 0) {
        int x = swsum[lane];
        for (int o = 1; o < 32; o <<= 1) {
            int t = __shfl_up_sync(0xffffffffu, x, o);
            if (lane >= o) x += t;
        }
        swsum[lane] = x;
    }
    __syncthreads();
    int incl = v + (wid ? swsum[wid - 1] : 0);
    int excl = incl - pairsum;
    int nv = swsum[31];
    int e0 = 2 * tid, e1 = 2 * tid + 1;
    int rank0 = excl;
    int rank1 = excl + val[0];
    int pos0 = val[0] ? rank0 : nv + (e0 - rank0);
    int pos1 = val[1] ? rank1 : nv + (e1 - rank1);
    if (e0 < PRE) {
        g_boxes[b][pos0] = box[0];
        g_area[b][pos0] = (box[0].z - box[0].x) * (box[0].w - box[0].y);
    }
    if (e1 < PRE) {
        g_boxes[b][pos1] = box[1];
        g_area[b][pos1] = (box[1].z - box[1].x) * (box[1].w - box[1].y);
    }
    if (tid == 0) g_nvalid[b] = nv;
}

__global__ void __launch_bounds__(64) k_mask() {
    int b = blockIdx.y;
    int t = threadIdx.x;
    int lin = blockIdx.x, rblk = 0;
    while (lin >= 32 - rblk) { lin -= 32 - rblk; rblk++; }
    int cblk = rblk + lin;
    int rb = rblk << 6, cb = cblk << 6;
    __shared__ float4 cbox[64];
    __shared__ float carea[64];
    {
        int j0 = cb + t;
        cbox[t] = (j0 < PRE) ? g_boxes[b][j0] : make_float4(-1.f, -1.f, -1.f, -1.f);
        carea[t] = (j0 < PRE) ? g_area[b][j0] : 0.f;
    }
    __syncthreads();
    int i = rb + t;
    if (i >= PRE) return;
    float4 bi = g_boxes[b][i];
    float areai = g_area[b][i];
    unsigned long long bits = 0ULL, amb = 0ULL;
    int c0 = (cblk == rblk) ? (t + 1) : 0;
#pragma unroll 8
    for (int c = c0; c < 64; c++) {
        float4 bj = cbox[c];
        float w = fmaxf(fminf(bi.z, bj.z) - fmaxf(bi.x, bj.x), 0.f);
        float h = fmaxf(fminf(bi.w, bj.w) - fmaxf(bi.y, bj.y), 0.f);
        float inter = w * h;
        float um = fmaxf((areai + carea[c]) - inter, 1e-8f);
        bool s1 = inter > 0.70000210f * um;
        bool a1 = (!s1) && (inter >= 0.69999790f * um);
        bits |= ((unsigned long long)s1) << c;
        amb |= ((unsigned long long)a1) << c;
    }
    while (amb) {
        int c = __ffsll(amb) - 1;
        amb &= amb - 1;
        float4 bj = cbox[c];
        float w = fmaxf(fminf(bi.z, bj.z) - fmaxf(bi.x, bj.x), 0.f);
        float h = fmaxf(fminf(bi.w, bj.w) - fmaxf(bi.y, bj.y), 0.f);
        float inter = w * h;
        float um = fmaxf((areai + carea[c]) - inter, 1e-8f);
        if (__fdiv_rn(inter, um) > 0.7f) bits |= 1ULL << c;
    }
    g_mask[b][i][cblk] = bits;
}

// Register-serial batched NMS scan. Lane 0 handles 16 rows per step fully in
// registers (statically-indexed m[16]); decision chain per row is a couple of
// ALU ops instead of LDS round-trips. All lanes then OR kept rows' mask words
// into rem in parallel. Decision order identical to sequential reference.
__global__ void __launch_bounds__(256) k_scan(float4* __restrict__ out) {
    __shared__ unsigned long long ring[4][16][32];
    __shared__ int sel[POST];
    __shared__ int skc;
    int b = blockIdx.x;
    int tid = threadIdx.x;
    if (tid < 32) {
        int lane = tid;
        int nv = g_nvalid[b];
        int lo = lane * 64;
        unsigned long long rem;
        if (nv <= lo) rem = ~0ULL;
        else if (nv >= lo + 64) rem = 0ULL;
        else rem = (~0ULL) << (nv - lo);
        for (int nb = 0; nb < 3; nb++) {
#pragma unroll
            for (int q = 0; q < 16; q++)
                CP8(smaddr(&ring[nb][q][lane]), &g_mask[b][nb * 16 + q][lane]);
            CPCOMMIT();
        }
        int limit = (PRE < nv) ? PRE : nv;
        int kc = 0, w = 0;
        unsigned long long r = 0ULL;
        for (int bt = 0; bt < PRE / 16; bt++) {
            CPWAIT2();
            __syncwarp();
            int base = bt * 16;
            if (base >= limit) break;
            if ((base & 63) == 0) {
                w = base >> 6;
                r = __shfl_sync(0xffffffffu, rem, w);
            }
            // lane 0: bulk-load 16 diagonal words, serial decide in registers
            unsigned long long m[16];
            unsigned keptm = 0;
            if (lane == 0) {
#pragma unroll
                for (int q = 0; q < 16; q++) m[q] = ring[bt & 3][q][w];
                int off = base & 63;
#pragma unroll
                for (int q = 0; q < 16; q++) {
                    int row = base + q;
                    bool keep = (row < limit) && !((r >> (off + q)) & 1ULL);
                    if (keep) {
                        if (kc < POST) sel[kc] = row;
                        kc++;
                        keptm |= 1u << q;
                        r |= m[q];
                    }
                }
            }
            keptm = __shfl_sync(0xffffffffu, keptm, 0);
            // parallel accumulate kept rows into rem (upper-tri words only)
            unsigned long long acc = 0ULL;
#pragma unroll
            for (int q = 0; q < 16; q++)
                if ((keptm >> q) & 1u) acc |= ring[bt & 3][q][lane];
            if (lane >= w) rem |= acc;
            kc = __shfl_sync(0xffffffffu, kc, 0);
            if (kc >= POST) break;
            int nb = bt + 3;
            if (nb < PRE / 16) {
#pragma unroll
                for (int q = 0; q < 16; q++)
                    CP8(smaddr(&ring[nb & 3][q][lane]), &g_mask[b][nb * 16 + q][lane]);
            }
            CPCOMMIT();
        }
        CPWAITALL();
        if (lane == 0) skc = (kc < POST) ? kc : POST;
    }
    __syncthreads();
    int kc = skc;
    for (int k = tid; k < POST; k += blockDim.x) {
        float4 v = make_float4(0.f, 0.f, 0.f, 0.f);
        if (k < kc) v = g_boxes[b][sel[k]];
        out[(size_t)b * POST + k] = v;
    }
}

extern "C" void kernel_launch(void* const* d_in, const int* in_sizes, int n_in,
                              void* d_out, int out_size) {
    const float* cls = (const float*)d_in[0];
    const float* reg = (const float*)d_in[1];
    const float* anchors = (const float*)d_in[2];
    float4* out = (float4*)d_out;

    k_zero<<<(BB * NBINS + 255) / 256, 256>>>();
    k_hist<<<dim3(37, BB), 256>>>(cls);
    k_cutA<<<BB, 256>>>();
    k_hist2<<<dim3(37, BB), 256>>>(cls);
    k_cutB<<<BB, 256>>>();
    k_compact<<<dim3(37, BB), 256>>>(cls);
    k_sortdecode<<<BB, 1024>>>(reg, anchors);
    k_mask<<<dim3(528, BB), 64>>>();
    k_scan<<<BB, 256>>>(out);
}

// round 6
// speedup vs baseline: 3.4978x; 1.0615x over previous
#include <cuda_runtime.h>
#include <math.h>

#define BB 16
#define NN 300000
#define NV 75000
#define NBLK 37
#define PRE 2000
#define POST 1000
#define CANDMAX 4096
#define MASKW 32
#define STAGE 1024

typedef unsigned long long ull;

__device__ unsigned g_phist[BB][NBLK][2048];
__device__ int g_cut[BB];
__device__ unsigned g_ccount[BB];
__device__ ull g_cand[BB][CANDMAX];
__device__ float4 g_boxes[BB][PRE];
__device__ float g_area[BB][PRE];
__device__ int g_nvalid[BB];
__device__ ull g_mask[BB][PRE][MASKW];

__device__ __forceinline__ unsigned keyf(float f) {
    unsigned u = __float_as_uint(f);
    return u ^ ((u >> 31) ? 0xFFFFFFFFu : 0x80000000u);
}

__device__ __forceinline__ unsigned smaddr(const void* p) {
    return (unsigned)__cvta_generic_to_shared(p);
}
#define CP8(dst, src) asm volatile("cp.async.ca.shared.global [%0], [%1], 8;" :: "r"(dst), "l"(src))
#define CPCOMMIT() asm volatile("cp.async.commit_group;")
#define CPWAIT2() asm volatile("cp.async.wait_group 2;")
#define CPWAITALL() asm volatile("cp.async.wait_all;")

// Per-block partial histograms (upper half of key space only) -> plain stores,
// no global zeroing kernel, no global atomics.
__global__ void __launch_bounds__(256) k_hist(const float* __restrict__ cls) {
    __shared__ unsigned sh[2048];
    int b = blockIdx.y;
    int t = threadIdx.x;
    for (int i = t; i < 2048; i += 256) sh[i] = 0u;
    __syncthreads();
    const float4* __restrict__ p = (const float4*)(cls + (size_t)b * NN);
    int base = blockIdx.x * 2048;
    if (base + 2048 <= NV) {
        float4 v[8];
#pragma unroll
        for (int k = 0; k < 8; k++) v[k] = p[base + t + 256 * k];
#pragma unroll
        for (int k = 0; k < 8; k++) {
            unsigned kk[4] = {keyf(v[k].x), keyf(v[k].y), keyf(v[k].z), keyf(v[k].w)};
#pragma unroll
            for (int q = 0; q < 4; q++)
                if (kk[q] >= 0x80000000u) atomicAdd(&sh[(kk[q] >> 20) - 2048], 1u);
        }
    } else {
        for (int k = 0; k < 8; k++) {
            int id = base + t + 256 * k;
            if (id < NV) {
                float4 v = p[id];
                unsigned kk[4] = {keyf(v.x), keyf(v.y), keyf(v.z), keyf(v.w)};
#pragma unroll
                for (int q = 0; q < 4; q++)
                    if (kk[q] >= 0x80000000u) atomicAdd(&sh[(kk[q] >> 20) - 2048], 1u);
            }
        }
    }
    __syncthreads();
    for (int i = t; i < 2048; i += 256) g_phist[b][blockIdx.x][i] = sh[i];
}

// Sum partials, find cut. In-kernel slow-path fallback (full histogram of all
// 300K values by this one block) only if the cut is not in the upper half —
// never taken for this data, costs nothing when skipped.
__global__ void __launch_bounds__(256) k_cut(const float* __restrict__ cls) {
    __shared__ unsigned hist[2048];
    __shared__ unsigned csum[256];
    __shared__ int sneed;
    int b = blockIdx.x;
    int t = threadIdx.x;
    unsigned loc[8] = {0, 0, 0, 0, 0, 0, 0, 0};
    for (int blk = 0; blk < NBLK; blk++) {
#pragma unroll
        for (int q = 0; q < 8; q++) loc[q] += g_phist[b][blk][t * 8 + q];
    }
    unsigned s = 0;
#pragma unroll
    for (int q = 0; q < 8; q++) { hist[t * 8 + q] = loc[q]; s += loc[q]; }
    csum[t] = s;
    __syncthreads();
    if (t == 0) {
        g_ccount[b] = 0u;
        unsigned acc = 0;
        int found = 0;
        for (int c = 255; c >= 0; c--) {
            if (acc + csum[c] >= PRE) {
                for (int i = 7; i >= 0; i--) {
                    unsigned h = hist[c * 8 + i];
                    if (acc + h >= PRE) { g_cut[b] = 2048 + c * 8 + i; found = 1; break; }
                    acc += h;
                }
                break;
            }
            acc += csum[c];
        }
        sneed = !found;
        if (!found) g_cut[b] = 0;
    }
    __syncthreads();
    if (sneed) {  // cold fallback: full 4096-bin histogram by this block
        __shared__ unsigned fh[4096];
        for (int i = t; i < 4096; i += 256) fh[i] = 0u;
        __syncthreads();
        const float4* __restrict__ p = (const float4*)(cls + (size_t)b * NN);
        for (int id = t; id < NV; id += 256) {
            float4 v = p[id];
            atomicAdd(&fh[keyf(v.x) >> 20], 1u);
            atomicAdd(&fh[keyf(v.y) >> 20], 1u);
            atomicAdd(&fh[keyf(v.z) >> 20], 1u);
            atomicAdd(&fh[keyf(v.w) >> 20], 1u);
        }
        __syncthreads();
        unsigned s2 = 0;
        for (int q = 0; q < 16; q++) s2 += fh[t * 16 + q];
        csum[t] = s2;
        __syncthreads();
        if (t == 0) {
            unsigned acc = 0;
            for (int c = 255; c >= 0; c--) {
                if (acc + csum[c] >= PRE) {
                    for (int i = 15; i >= 0; i--) {
                        unsigned h = fh[c * 16 + i];
                        if (acc + h >= PRE) { g_cut[b] = c * 16 + i; return; }
                        acc += h;
                    }
                    return;
                }
                acc += csum[c];
            }
            g_cut[b] = 0;
        }
    }
}

__global__ void __launch_bounds__(256) k_compact(const float* __restrict__ cls) {
    __shared__ ull stage[STAGE];
    __shared__ unsigned s_cnt, s_base;
    int b = blockIdx.y;
    int t = threadIdx.x;
    int cut = g_cut[b];
    if (t == 0) s_cnt = 0u;
    __syncthreads();
    const float4* __restrict__ p = (const float4*)(cls + (size_t)b * NN);
    int base = blockIdx.x * 2048;
    if (base + 2048 <= NV) {
        float4 v[8];
#pragma unroll
        for (int k = 0; k < 8; k++) v[k] = p[base + t + 256 * k];
#pragma unroll
        for (int k = 0; k < 8; k++) {
            int id = base + t + 256 * k;
            unsigned kk[4] = {keyf(v[k].x), keyf(v[k].y), keyf(v[k].z), keyf(v[k].w)};
#pragma unroll
            for (int q = 0; q < 4; q++) {
                if ((int)(kk[q] >> 20) >= cut) {
                    unsigned r = atomicAdd(&s_cnt, 1u);
                    if (r < STAGE)
                        stage[r] = ((ull)kk[q] << 32) | (unsigned)(~(4 * id + q));
                }
            }
        }
    } else {
        for (int k = 0; k < 8; k++) {
            int id = base + t + 256 * k;
            if (id < NV) {
                float4 v = p[id];
                unsigned kk[4] = {keyf(v.x), keyf(v.y), keyf(v.z), keyf(v.w)};
#pragma unroll
                for (int q = 0; q < 4; q++) {
                    if ((int)(kk[q] >> 20) >= cut) {
                        unsigned r = atomicAdd(&s_cnt, 1u);
                        if (r < STAGE)
                            stage[r] = ((ull)kk[q] << 32) | (unsigned)(~(4 * id + q));
                    }
                }
            }
        }
    }
    __syncthreads();
    if (t == 0) {
        unsigned c = s_cnt < STAGE ? s_cnt : STAGE;
        s_base = atomicAdd(&g_ccount[b], c);
    }
    __syncthreads();
    unsigned c = s_cnt < STAGE ? s_cnt : STAGE;
    for (unsigned r = t; r < c; r += 256) {
        unsigned pos = s_base + r;
        if (pos < CANDMAX) g_cand[b][pos] = stage[r];
    }
}

// Register/shfl-blocked bitonic sort: 4 elements/thread. j=1,2 intra-thread,
// j=4..64 via shfl_xor, only j>=128 via shared (15 passes vs 78).
#define CSW(a, c, d) { if ((d) ? ((a) < (c)) : ((a) > (c))) { ull _t = (a); (a) = (c); (c) = _t; } }
#define KM(e, o) ((kmax) ? ((e) > (o) ? (e) : (o)) : ((e) < (o) ? (e) : (o)))

__global__ void __launch_bounds__(1024)
k_sortdecode(const float* __restrict__ reg, const float* __restrict__ anchors) {
    __shared__ ull sk[CANDMAX];
    __shared__ int swsum[32];
    int b = blockIdx.x;
    int tid = threadIdx.x;
    unsigned n = g_ccount[b];
    if (n > CANDMAX) n = CANDMAX;
    int base4 = 4 * tid;
    ull e0 = (base4 + 0 < (int)n) ? g_cand[b][base4 + 0] : 0ULL;
    ull e1 = (base4 + 1 < (int)n) ? g_cand[b][base4 + 1] : 0ULL;
    ull e2 = (base4 + 2 < (int)n) ? g_cand[b][base4 + 2] : 0ULL;
    ull e3 = (base4 + 3 < (int)n) ? g_cand[b][base4 + 3] : 0ULL;
    // k=2: pairs (0,1) desc, (2,3) asc
    CSW(e0, e1, true);
    CSW(e2, e3, false);
    for (int k = 4; k <= CANDMAX; k <<= 1) {
        bool desc = ((base4 & k) == 0);
        for (int j = k >> 1; j >= 128; j >>= 1) {
            sk[base4] = e0; sk[base4 + 1] = e1; sk[base4 + 2] = e2; sk[base4 + 3] = e3;
            __syncthreads();
            int m = j >> 2;
            int pt = 4 * (tid ^ m);
            bool kmax = (desc != ((tid & m) != 0));
            ull o0 = sk[pt], o1 = sk[pt + 1], o2 = sk[pt + 2], o3 = sk[pt + 3];
            e0 = KM(e0, o0); e1 = KM(e1, o1); e2 = KM(e2, o2); e3 = KM(e3, o3);
            __syncthreads();
        }
        int jstart = (k >> 1) < 64 ? (k >> 1) : 64;
        for (int j = jstart; j >= 4; j >>= 1) {
            int m = j >> 2;
            bool kmax = (desc != ((tid & m) != 0));
            ull o0 = __shfl_xor_sync(0xffffffffu, e0, m);
            ull o1 = __shfl_xor_sync(0xffffffffu, e1, m);
            ull o2 = __shfl_xor_sync(0xffffffffu, e2, m);
            ull o3 = __shfl_xor_sync(0xffffffffu, e3, m);
            e0 = KM(e0, o0); e1 = KM(e1, o1); e2 = KM(e2, o2); e3 = KM(e3, o3);
        }
        // j=2: pairs (0,2),(1,3); j=1: pairs (0,1),(2,3) — direction desc
        CSW(e0, e2, desc); CSW(e1, e3, desc);
        CSW(e0, e1, desc); CSW(e2, e3, desc);
    }
    sk[base4] = e0; sk[base4 + 1] = e1; sk[base4 + 2] = e2; sk[base4 + 3] = e3;
    __syncthreads();

    float4 box[2];
    int val[2];
#pragma unroll
    for (int q = 0; q < 2; q++) {
        int e = 2 * tid + q;
        val[q] = 0;
        box[q] = make_float4(0.f, 0.f, 0.f, 0.f);
        if (e < PRE) {
            unsigned idx = ~(unsigned)(sk[e] & 0xFFFFFFFFULL);
            const float* a = anchors + ((size_t)b * NN + idx) * 4;
            const float* r = reg + ((size_t)b * NN + idx) * 4;
            float a0 = a[0], a1 = a[1], a2 = a[2], a3 = a[3];
            float dx = r[0], dy = r[1], dw = r[2], dh = r[3];
            float aw = a2 - a0, ah = a3 - a1;
            float acx = a0 + 0.5f * aw, acy = a1 + 0.5f * ah;
            float pcx = dx * aw + acx, pcy = dy * ah + acy;
            float pw = expf(dw) * aw, ph = expf(dh) * ah;
            float x1 = pcx - 0.5f * pw, y1 = pcy - 0.5f * ph;
            float x2 = pcx + 0.5f * pw, y2 = pcy + 0.5f * ph;
            x1 = fminf(fmaxf(x1, 0.f), 1333.f);
            y1 = fminf(fmaxf(y1, 0.f), 800.f);
            x2 = fminf(fmaxf(x2, 0.f), 1333.f);
            y2 = fminf(fmaxf(y2, 0.f), 800.f);
            float w = x2 - x1, h = y2 - y1;
            val[q] = (w >= 0.001f && h >= 0.001f) ? 1 : 0;
            box[q] = make_float4(x1, y1, x2, y2);
        }
    }
    int pairsum = val[0] + val[1];
    int lane = tid & 31, wid = tid >> 5;
    int v = pairsum;
    for (int o = 1; o < 32; o <<= 1) {
        int t2 = __shfl_up_sync(0xffffffffu, v, o);
        if (lane >= o) v += t2;
    }
    if (lane == 31) swsum[wid] = v;
    __syncthreads();
    if (wid == 0) {
        int x = swsum[lane];
        for (int o = 1; o < 32; o <<= 1) {
            int t2 = __shfl_up_sync(0xffffffffu, x, o);
            if (lane >= o) x += t2;
        }
        swsum[lane] = x;
    }
    __syncthreads();
    int incl = v + (wid ? swsum[wid - 1] : 0);
    int excl = incl - pairsum;
    int nv = swsum[31];
    int ea = 2 * tid, eb = 2 * tid + 1;
    int rank0 = excl;
    int rank1 = excl + val[0];
    int pos0 = val[0] ? rank0 : nv + (ea - rank0);
    int pos1 = val[1] ? rank1 : nv + (eb - rank1);
    if (ea < PRE) {
        g_boxes[b][pos0] = box[0];
        g_area[b][pos0] = (box[0].z - box[0].x) * (box[0].w - box[0].y);
    }
    if (eb < PRE) {
        g_boxes[b][pos1] = box[1];
        g_area[b][pos1] = (box[1].z - box[1].x) * (box[1].w - box[1].y);
    }
    if (tid == 0) g_nvalid[b] = nv;
}

__global__ void __launch_bounds__(64) k_mask() {
    int b = blockIdx.y;
    int t = threadIdx.x;
    int lin = blockIdx.x, rblk = 0;
    while (lin >= 32 - rblk) { lin -= 32 - rblk; rblk++; }
    int cblk = rblk + lin;
    int rb = rblk << 6, cb = cblk << 6;
    __shared__ float4 cbox[64];
    __shared__ float carea[64];
    {
        int j0 = cb + t;
        cbox[t] = (j0 < PRE) ? g_boxes[b][j0] : make_float4(-1.f, -1.f, -1.f, -1.f);
        carea[t] = (j0 < PRE) ? g_area[b][j0] : 0.f;
    }
    __syncthreads();
    int i = rb + t;
    if (i >= PRE) return;
    float4 bi = g_boxes[b][i];
    float areai = g_area[b][i];
    ull bits = 0ULL, amb = 0ULL;
    int c0 = (cblk == rblk) ? (t + 1) : 0;
#pragma unroll 8
    for (int c = c0; c < 64; c++) {
        float4 bj = cbox[c];
        float w = fmaxf(fminf(bi.z, bj.z) - fmaxf(bi.x, bj.x), 0.f);
        float h = fmaxf(fminf(bi.w, bj.w) - fmaxf(bi.y, bj.y), 0.f);
        float inter = w * h;
        float um = fmaxf((areai + carea[c]) - inter, 1e-8f);
        bool s1 = inter > 0.70000210f * um;
        bool a1 = (!s1) && (inter >= 0.69999790f * um);
        bits |= ((ull)s1) << c;
        amb |= ((ull)a1) << c;
    }
    while (amb) {
        int c = __ffsll(amb) - 1;
        amb &= amb - 1;
        float4 bj = cbox[c];
        float w = fmaxf(fminf(bi.z, bj.z) - fmaxf(bi.x, bj.x), 0.f);
        float h = fmaxf(fminf(bi.w, bj.w) - fmaxf(bi.y, bj.y), 0.f);
        float inter = w * h;
        float um = fmaxf((areai + carea[c]) - inter, 1e-8f);
        if (__fdiv_rn(inter, um) > 0.7f) bits |= 1ULL << c;
    }
    g_mask[b][i][cblk] = bits;
}

__global__ void __launch_bounds__(256) k_scan(float4* __restrict__ out) {
    __shared__ ull ring[4][16][32];
    __shared__ int sel[POST];
    __shared__ int skc;
    int b = blockIdx.x;
    int tid = threadIdx.x;
    if (tid < 32) {
        int lane = tid;
        int nv = g_nvalid[b];
        int lo = lane * 64;
        ull rem;
        if (nv <= lo) rem = ~0ULL;
        else if (nv >= lo + 64) rem = 0ULL;
        else rem = (~0ULL) << (nv - lo);
        for (int nb = 0; nb < 3; nb++) {
#pragma unroll
            for (int q = 0; q < 16; q++)
                CP8(smaddr(&ring[nb][q][lane]), &g_mask[b][nb * 16 + q][lane]);
            CPCOMMIT();
        }
        int limit = (PRE < nv) ? PRE : nv;
        int kc = 0, w = 0;
        ull r = 0ULL;
        for (int bt = 0; bt < PRE / 16; bt++) {
            CPWAIT2();
            __syncwarp();
            int base = bt * 16;
            if (base >= limit) break;
            if ((base & 63) == 0) {
                w = base >> 6;
                r = __shfl_sync(0xffffffffu, rem, w);
            }
            ull m[16];
            unsigned keptm = 0;
            if (lane == 0) {
#pragma unroll
                for (int q = 0; q < 16; q++) m[q] = ring[bt & 3][q][w];
                int off = base & 63;
#pragma unroll
                for (int q = 0; q < 16; q++) {
                    int row = base + q;
                    bool keep = (row < limit) && !((r >> (off + q)) & 1ULL);
                    if (keep) {
                        if (kc < POST) sel[kc] = row;
                        kc++;
                        keptm |= 1u << q;
                        r |= m[q];
                    }
                }
            }
            keptm = __shfl_sync(0xffffffffu, keptm, 0);
            ull acc = 0ULL;
#pragma unroll
            for (int q = 0; q < 16; q++)
                if ((keptm >> q) & 1u) acc |= ring[bt & 3][q][lane];
            if (lane >= w) rem |= acc;
            kc = __shfl_sync(0xffffffffu, kc, 0);
            if (kc >= POST) break;
            int nb = bt + 3;
            if (nb < PRE / 16) {
#pragma unroll
                for (int q = 0; q < 16; q++)
                    CP8(smaddr(&ring[nb & 3][q][lane]), &g_mask[b][nb * 16 + q][lane]);
            }
            CPCOMMIT();
        }
        CPWAITALL();
        if (lane == 0) skc = (kc < POST) ? kc : POST;
    }
    __syncthreads();
    int kc = skc;
    for (int k = tid; k < POST; k += blockDim.x) {
        float4 v = make_float4(0.f, 0.f, 0.f, 0.f);
        if (k < kc) v = g_boxes[b][sel[k]];
        out[(size_t)b * POST + k] = v;
    }
}

extern "C" void kernel_launch(void* const* d_in, const int* in_sizes, int n_in,
                              void* d_out, int out_size) {
    const float* cls = (const float*)d_in[0];
    const float* reg = (const float*)d_in[1];
    const float* anchors = (const float*)d_in[2];
    float4* out = (float4*)d_out;

    k_hist<<<dim3(NBLK, BB), 256>>>(cls);
    k_cut<<<BB, 256>>>(cls);
    k_compact<<<dim3(NBLK, BB), 256>>>(cls);
    k_sortdecode<<<BB, 1024>>>(reg, anchors);
    k_mask<<<dim3(528, BB), 64>>>();
    k_scan<<<BB, 256>>>(out);
}